// round 1
// baseline (speedup 1.0000x reference)
#include <cuda_runtime.h>
#include <cstdint>

// Problem constants
#define N_IMG   16
#define C_IN    64
#define C_OUT   64
#define HH      128
#define WW      128
#define KK      3
#define W_ELEMS (C_OUT * C_IN * KK * KK)   // 36864

// Persistent scratch (no allocations allowed)
__device__ float g_scale[2];                 // scale for w, w_child
__device__ float g_weff[W_ELEMS];            // fused effective weights, layout [c][o][k]
__device__ float g_beff[C_OUT];              // fused bias

// ---------------------------------------------------------------------------
// packed f32x2 helpers (sm_103a FFMA2 path)
// ---------------------------------------------------------------------------
__device__ __forceinline__ unsigned long long pack2(float lo, float hi) {
    unsigned long long r;
    unsigned int a = __float_as_uint(lo), b = __float_as_uint(hi);
    asm("mov.b64 %0, {%1, %2};" : "=l"(r) : "r"(a), "r"(b));
    return r;
}
__device__ __forceinline__ void unpack2(unsigned long long v, float& lo, float& hi) {
    unsigned int a, b;
    asm("mov.b64 {%0, %1}, %2;" : "=r"(a), "=r"(b) : "l"(v));
    lo = __uint_as_float(a);
    hi = __uint_as_float(b);
}
__device__ __forceinline__ unsigned long long ffma2(unsigned long long a,
                                                    unsigned long long b,
                                                    unsigned long long c) {
    unsigned long long d;
    asm("fma.rn.f32x2 %0, %1, %2, %3;" : "=l"(d) : "l"(a), "l"(b), "l"(c));
    return d;
}

// ---------------------------------------------------------------------------
// Kernel 1: per-tensor scale = max(mean(|w|), 1e-5), fp64 accumulation
// ---------------------------------------------------------------------------
__global__ void scale_kernel(const float* __restrict__ w,
                             const float* __restrict__ wc) {
    const float* p = (blockIdx.x == 0) ? w : wc;
    __shared__ double red[256];
    double s = 0.0;
    for (int i = threadIdx.x; i < W_ELEMS; i += 256)
        s += (double)fabsf(p[i]);
    red[threadIdx.x] = s;
    __syncthreads();
    for (int off = 128; off > 0; off >>= 1) {
        if (threadIdx.x < off) red[threadIdx.x] += red[threadIdx.x + off];
        __syncthreads();
    }
    if (threadIdx.x == 0)
        g_scale[blockIdx.x] = fmaxf((float)(red[0] / (double)W_ELEMS), 1e-5f);
}

// ---------------------------------------------------------------------------
// Kernel 2: fuse weights: Weff = Q(w) + sigmoid(gate)*Q(w_child)
// input layout [o][c][kh][kw] -> scratch layout [c][o][k]  (k = kh*3+kw)
// ---------------------------------------------------------------------------
__global__ void prep_kernel(const float* __restrict__ w,
                            const float* __restrict__ b,
                            const float* __restrict__ wc,
                            const float* __restrict__ bc,
                            const float* __restrict__ gate) {
    int i = blockIdx.x * 256 + threadIdx.x;
    float g = 1.0f / (1.0f + expf(-gate[0]));
    if (i < W_ELEMS) {
        float s1 = g_scale[0], s2 = g_scale[1];
        // rintf == round-half-to-even == jnp.round
        float q1 = fminf(fmaxf(rintf(w[i]  / s1), -1.0f), 1.0f) * s1;
        float q2 = fminf(fmaxf(rintf(wc[i] / s2), -1.0f), 1.0f) * s2;
        int o = i / (C_IN * 9);
        int r = i - o * (C_IN * 9);
        int c = r / 9;
        int k = r - c * 9;
        g_weff[c * (C_OUT * 9) + o * 9 + k] = q1 + g * q2;
    }
    if (i < C_OUT)
        g_beff[i] = b[i] + g * bc[i];
}

// ---------------------------------------------------------------------------
// Kernel 3: direct 3x3 conv, pad 1.
// Grid: x = oc-group (4, fastest -> L2 x-tile reuse), y = spatial tile (16),
//       z = image (16).  Block: 256 threads.
// Each block: 32x32 output pixels x 16 output channels.
// Each thread: 2x2 pixel micro-tile x 16 oc, packed-f32x2 accumulators.
// ---------------------------------------------------------------------------
#define XS_STRIDE 35   // 34 cols + pad (odd stride)

__global__ __launch_bounds__(256, 2)
void conv_kernel(const float* __restrict__ x, float* __restrict__ out) {
    const int og = blockIdx.x;            // 0..3   (16 oc each)
    const int sp = blockIdx.y;            // 0..15  spatial tile
    const int n  = blockIdx.z;            // 0..15
    const int sx = sp & 3, sy = sp >> 2;

    const int tid = threadIdx.x;
    const int tx = tid & 15;              // 0..15 -> 2*tx pixel col
    const int ty = tid >> 4;              // 0..15 -> 2*ty pixel row

    __shared__ float xs[34 * XS_STRIDE];
    __shared__ float wsm[16 * 9];

    unsigned long long acc[16][2];
#pragma unroll
    for (int ol = 0; ol < 16; ++ol) { acc[ol][0] = 0ull; acc[ol][1] = 0ull; }

    const float* xn = x + (size_t)n * C_IN * HH * WW;
    const int gx0 = sx * 32 - 1;
    const int gy0 = sy * 32 - 1;

    for (int c = 0; c < C_IN; ++c) {
        const float* xc = xn + (size_t)c * (HH * WW);
        // stage 34x34 input patch (zero-padded at borders)
        for (int i = tid; i < 34 * 34; i += 256) {
            int r = i / 34;
            int col = i - r * 34;
            int gy = gy0 + r, gx = gx0 + col;
            float v = 0.0f;
            if ((unsigned)gy < (unsigned)HH && (unsigned)gx < (unsigned)WW)
                v = xc[gy * WW + gx];
            xs[r * XS_STRIDE + col] = v;
        }
        // stage 16 oc x 9 weights for this input channel
        if (tid < 144)
            wsm[tid] = g_weff[c * (C_OUT * 9) + og * 144 + tid];
        __syncthreads();

        // 4x4 input registers cover all 9 taps of the 2x2 micro-tile
        float xr[4][4];
#pragma unroll
        for (int i = 0; i < 4; ++i)
#pragma unroll
            for (int j = 0; j < 4; ++j)
                xr[i][j] = xs[(2 * ty + i) * XS_STRIDE + 2 * tx + j];

#pragma unroll
        for (int kh = 0; kh < 3; ++kh) {
#pragma unroll
            for (int kw = 0; kw < 3; ++kw) {
                unsigned long long xp0 = pack2(xr[kh + 0][kw], xr[kh + 0][kw + 1]);
                unsigned long long xp1 = pack2(xr[kh + 1][kw], xr[kh + 1][kw + 1]);
                const int k = kh * 3 + kw;
#pragma unroll
                for (int ol = 0; ol < 16; ++ol) {
                    float wv = wsm[ol * 9 + k];
                    unsigned long long wp = pack2(wv, wv);
                    acc[ol][0] = ffma2(xp0, wp, acc[ol][0]);
                    acc[ol][1] = ffma2(xp1, wp, acc[ol][1]);
                }
            }
        }
        __syncthreads();
    }

    // epilogue: add fused bias, coalesced float2 stores
    const int ybase = sy * 32 + 2 * ty;
    const int xbase = sx * 32 + 2 * tx;
#pragma unroll
    for (int ol = 0; ol < 16; ++ol) {
        float bv = g_beff[og * 16 + ol];
        size_t obase = (((size_t)n * C_OUT + og * 16 + ol) * HH + ybase) * WW + xbase;
#pragma unroll
        for (int py = 0; py < 2; ++py) {
            float lo, hi;
            unpack2(acc[ol][py], lo, hi);
            float2 v = make_float2(lo + bv, hi + bv);
            *reinterpret_cast<float2*>(out + obase + (size_t)py * WW) = v;
        }
    }
}

// ---------------------------------------------------------------------------
extern "C" void kernel_launch(void* const* d_in, const int* in_sizes, int n_in,
                              void* d_out, int out_size) {
    const float* x  = (const float*)d_in[0];
    const float* w  = (const float*)d_in[1];
    const float* b  = (const float*)d_in[2];
    const float* wc = (const float*)d_in[3];
    const float* bc = (const float*)d_in[4];
    const float* gt = (const float*)d_in[5];
    float* out = (float*)d_out;

    scale_kernel<<<2, 256>>>(w, wc);
    prep_kernel<<<(W_ELEMS + 255) / 256, 256>>>(w, b, wc, bc, gt);
    dim3 grid(4, 16, N_IMG);
    conv_kernel<<<grid, 256>>>(x, out);
}